// round 5
// baseline (speedup 1.0000x reference)
#include <cuda_runtime.h>
#include <math.h>

// ---------------------------------------------------------------------------
// CMAF fused block, round 5:
//   - Resident-K GEMM (K=128): A tf32-converted once in smem, W double-buffered
//     cp.async across jobs, ONE barrier per job. Used by gf/qkv/outproj/ffn1.
//   - Pipelined GEMM (BK=32, 3 stages) for spatial (K=1280) and ffn2 (K=256).
//   - LayerNorm fused into GEMM epilogues (cross-warp smem reduce) -> no k_ln.
// ---------------------------------------------------------------------------

#define MAXB 65536
#define RPAD 132                      // resident row pad (words)
#define PPAD 36                       // pipelined row pad (words)
#define RSMEM (3 * 128 * RPAD * 4)    // 202752 B : A + 2 W bufs
#define PSMEM (3 * 2 * 128 * PPAD * 4)// 110592 B : 3 stages x (A+W)

__device__ __align__(16) float g_P [MAXB * 3 * 128];
__device__ __align__(16) float g_q [MAXB * 3 * 128];
__device__ __align__(16) float g_k [MAXB * 6 * 128];
__device__ __align__(16) float g_v [MAXB * 6 * 128];
__device__ __align__(16) float g_o [MAXB * 3 * 128];
__device__ __align__(16) float g_x1[MAXB * 3 * 128];
__device__ __align__(16) float g_h [MAXB * 3 * 256];
__device__ __align__(16) float g_x2[MAXB * 3 * 128];

// QKV jobs per source stream s: {w_off, b_off, buf_id, out_off} (validated R4)
__constant__ int qkv_jobs[3][5][4] = {
    { {     0,    0, 0,   0}, { 65536,  512, 1, 256}, { 81920,  640, 2, 256},
      {114688,  896, 1, 512}, {131072, 1024, 2, 512} },
    { { 49152,  384, 0, 128}, { 16384,  128, 1,   0}, { 32768,  256, 2,   0},
      {114688,  896, 1, 640}, {131072, 1024, 2, 640} },
    { { 98304,  768, 0, 256}, { 16384,  128, 1, 128}, { 32768,  256, 2, 128},
      { 65536,  512, 1, 384}, { 81920,  640, 2, 384} },
};

__device__ __forceinline__ unsigned f2tf(float f) {
    unsigned u;
    asm("cvt.rna.tf32.f32 %0, %1;" : "=r"(u) : "f"(f));
    return u;
}

__device__ __forceinline__ void mma8(float c[4], const unsigned a[4], const unsigned b[2]) {
    asm volatile(
        "mma.sync.aligned.m16n8k8.row.col.f32.tf32.tf32.f32 "
        "{%0,%1,%2,%3}, {%4,%5,%6,%7}, {%8,%9}, {%0,%1,%2,%3};\n"
        : "+f"(c[0]), "+f"(c[1]), "+f"(c[2]), "+f"(c[3])
        : "r"(a[0]), "r"(a[1]), "r"(a[2]), "r"(a[3]), "r"(b[0]), "r"(b[1]));
}

__device__ __forceinline__ void cp16(unsigned smem_dst, const void* gsrc) {
    asm volatile("cp.async.cg.shared.global [%0], [%1], 16;\n"
                 :: "r"(smem_dst), "l"(gsrc));
}
__device__ __forceinline__ void cp_commit() {
    asm volatile("cp.async.commit_group;\n");
}
template <int N>
__device__ __forceinline__ void cp_wait() {
    asm volatile("cp.async.wait_group %0;\n" :: "n"(N));
}

// ---------------------------------------------------------------------------
// Shared epilogue. EPI: 0=bias, 1=bias+gelu, 2=bias+LN+addv, 3=bias+resid+LN
// Thread layout: 8 warps 2(m)x4(n), warp tile 64x32; acc[mt][nt][4].
// ---------------------------------------------------------------------------
template <int EPI>
__device__ __forceinline__ void epi_store(
    float acc[4][4][4],
    const float* __restrict__ bias,
    const float* __restrict__ lng, const float* __restrict__ lnb,
    const float* __restrict__ addv,
    const float* __restrict__ resid, int rstride,
    float* __restrict__ out, int ostride, int m0, int M)
{
    __shared__ float2 pbuf[128][4];
    const int tid = threadIdx.x, wid = tid >> 5, lane = tid & 31;
    const int wm = (wid & 1) * 64, wn = (wid >> 1) * 32, wq = wid >> 1;
    const int g = lane >> 2, t4 = lane & 3;

    float b2[4][2];
#pragma unroll
    for (int nt = 0; nt < 4; ++nt) {
        const int col = wn + nt * 8 + t4 * 2;
        b2[nt][0] = bias[col]; b2[nt][1] = bias[col + 1];
    }

    if (EPI <= 1) {
#pragma unroll
        for (int mt = 0; mt < 4; ++mt)
#pragma unroll
        for (int hf = 0; hf < 2; ++hf) {
            const int r = m0 + wm + mt * 16 + hf * 8 + g;
            if (r < M) {
                float* orow = out + (long)r * ostride;
#pragma unroll
                for (int nt = 0; nt < 4; ++nt) {
                    const int col = wn + nt * 8 + t4 * 2;
                    float c0 = acc[mt][nt][hf * 2 + 0] + b2[nt][0];
                    float c1 = acc[mt][nt][hf * 2 + 1] + b2[nt][1];
                    if (EPI == 1) {
                        c0 = c0 * 0.5f * (1.0f + erff(c0 * 0.70710678118654752f));
                        c1 = c1 * 0.5f * (1.0f + erff(c1 * 0.70710678118654752f));
                    }
                    *(float2*)(orow + col) = make_float2(c0, c1);
                }
            }
        }
        return;
    }

    // LN path: add bias (+resid), partial row sums, cross-warp reduce in smem
#pragma unroll
    for (int mt = 0; mt < 4; ++mt)
#pragma unroll
    for (int hf = 0; hf < 2; ++hf) {
        const int lr = wm + mt * 16 + hf * 8 + g;
        const int r  = m0 + lr;
        float s = 0.f, s2 = 0.f;
        const float* rrow = (EPI == 3) ? resid + (long)min(r, M - 1) * rstride : (const float*)0;
#pragma unroll
        for (int nt = 0; nt < 4; ++nt) {
            const int col = wn + nt * 8 + t4 * 2;
            float c0 = acc[mt][nt][hf * 2 + 0] + b2[nt][0];
            float c1 = acc[mt][nt][hf * 2 + 1] + b2[nt][1];
            if (EPI == 3) {
                const float2 rv = *(const float2*)(rrow + col);
                c0 += rv.x; c1 += rv.y;
            }
            acc[mt][nt][hf * 2 + 0] = c0; acc[mt][nt][hf * 2 + 1] = c1;
            s += c0 + c1; s2 += c0 * c0 + c1 * c1;
        }
        s  += __shfl_xor_sync(0xffffffffu, s, 1);
        s  += __shfl_xor_sync(0xffffffffu, s, 2);
        s2 += __shfl_xor_sync(0xffffffffu, s2, 1);
        s2 += __shfl_xor_sync(0xffffffffu, s2, 2);
        if (t4 == 0) pbuf[lr][wq] = make_float2(s, s2);
    }
    __syncthreads();
#pragma unroll
    for (int mt = 0; mt < 4; ++mt)
#pragma unroll
    for (int hf = 0; hf < 2; ++hf) {
        const int lr = wm + mt * 16 + hf * 8 + g;
        const int r  = m0 + lr;
        const float2 p0 = pbuf[lr][0], p1 = pbuf[lr][1], p2 = pbuf[lr][2], p3 = pbuf[lr][3];
        const float s    = p0.x + p1.x + p2.x + p3.x;
        const float s2   = p0.y + p1.y + p2.y + p3.y;
        const float mean = s * 0.0078125f;
        const float var  = s2 * 0.0078125f - mean * mean;
        const float rs   = rsqrtf(var + 1e-5f);
        if (r < M) {
            float* orow = out + (long)r * ostride;
#pragma unroll
            for (int nt = 0; nt < 4; ++nt) {
                const int col = wn + nt * 8 + t4 * 2;
                float o0 = (acc[mt][nt][hf * 2 + 0] - mean) * rs * lng[col]     + lnb[col];
                float o1 = (acc[mt][nt][hf * 2 + 1] - mean) * rs * lng[col + 1] + lnb[col + 1];
                if (EPI == 2) { o0 += addv[col]; o1 += addv[col + 1]; }
                *(float2*)(orow + col) = make_float2(o0, o1);
            }
        }
    }
}

// ---------------------------------------------------------------------------
// Resident-K (=128) pieces
// ---------------------------------------------------------------------------
__device__ __forceinline__ void stage_A_tf32(
    const float* __restrict__ A, int lda, int m0, int M, unsigned* As)
{
    const int tid = threadIdx.x, r = tid >> 1, h = tid & 1;
    const float* src = A + (long)min(m0 + r, M - 1) * lda + h * 64;
    unsigned* dst = As + r * RPAD + h * 64;
#pragma unroll
    for (int j = 0; j < 16; ++j) {
        const float4 v = *(const float4*)(src + 4 * j);
        uint4 u;
        u.x = f2tf(v.x); u.y = f2tf(v.y); u.z = f2tf(v.z); u.w = f2tf(v.w);
        *(uint4*)(dst + 4 * j) = u;
    }
}

__device__ __forceinline__ void stage_W_async(const float* __restrict__ W, float* Wbuf)
{
    const int tid = threadIdx.x, r = tid >> 1, h = tid & 1;
    const float* src = W + r * 128 + h * 64;
    const unsigned dst = (unsigned)__cvta_generic_to_shared(Wbuf + r * RPAD + h * 64);
#pragma unroll
    for (int j = 0; j < 16; ++j) cp16(dst + 16 * j, src + 4 * j);
}

__device__ __forceinline__ void resident_mainloop(
    const unsigned* __restrict__ As, const float* __restrict__ Ws,
    int wm, int wn, int g, int t4, float acc[4][4][4])
{
#pragma unroll 4
    for (int ks = 0; ks < 16; ++ks) {
        const int k = ks * 8;
        unsigned af[4][4];
#pragma unroll
        for (int mt = 0; mt < 4; ++mt) {
            const unsigned* a0 = As + (wm + mt * 16 + g) * RPAD + k + t4;
            const unsigned* a1 = a0 + 8 * RPAD;
            af[mt][0] = a0[0]; af[mt][1] = a1[0]; af[mt][2] = a0[4]; af[mt][3] = a1[4];
        }
        unsigned bf[4][2];
#pragma unroll
        for (int nt = 0; nt < 4; ++nt) {
            const float* w0 = Ws + (wn + nt * 8 + g) * RPAD + k + t4;
            bf[nt][0] = f2tf(w0[0]); bf[nt][1] = f2tf(w0[4]);
        }
#pragma unroll
        for (int mt = 0; mt < 4; ++mt)
#pragma unroll
        for (int nt = 0; nt < 4; ++nt)
            mma8(acc[mt][nt], af[mt], bf[nt]);
    }
}

// ---------------------------------------------------------------------------
// Pipelined GEMM (BK=32, 3 stages) — for K=1280 (spatial) and K=256 (ffn2)
// ---------------------------------------------------------------------------
template <int EPI>
__device__ __forceinline__ void pipe_gemm(
    const float* __restrict__ A, int lda,
    const float* __restrict__ W, int K,
    const float* __restrict__ bias,
    const float* __restrict__ lng, const float* __restrict__ lnb,
    const float* __restrict__ addv,
    const float* __restrict__ resid, int rstride,
    float* __restrict__ out, int ostride, int m0, int M)
{
    extern __shared__ float smem[];
    const int tid = threadIdx.x;
    const int r = tid >> 1, h = tid & 1;
    const float* Aptr = A + (long)min(m0 + r, M - 1) * lda + h * 16;
    const float* Wptr = W + (long)r * K + h * 16;
    unsigned sa[3], sw[3];
#pragma unroll
    for (int st = 0; st < 3; ++st) {
        sa[st] = (unsigned)__cvta_generic_to_shared(&smem[(st * 128 + r) * PPAD + h * 16]);
        sw[st] = (unsigned)__cvta_generic_to_shared(&smem[((3 + st) * 128 + r) * PPAD + h * 16]);
    }
    const int wid = tid >> 5, lane = tid & 31;
    const int wm = (wid & 1) * 64, wn = (wid >> 1) * 32;
    const int g = lane >> 2, t4 = lane & 3;
    float acc[4][4][4] = {};
    const int ntiles = K >> 5;

#pragma unroll
    for (int p = 0; p < 2; ++p) {
        const int k0 = p * 32;
#pragma unroll
        for (int c = 0; c < 4; ++c) {
            cp16(sa[p] + c * 16, Aptr + k0 + c * 4);
            cp16(sw[p] + c * 16, Wptr + k0 + c * 4);
        }
        cp_commit();
    }

    int cur = 0;
    for (int t = 0; t < ntiles; ++t) {
        if (t + 2 < ntiles) cp_wait<1>(); else cp_wait<0>();
        __syncthreads();
        if (t + 2 < ntiles) {
            const int buf = (cur + 2 >= 3) ? cur - 1 : cur + 2;
            const int k0 = (t + 2) * 32;
#pragma unroll
            for (int c = 0; c < 4; ++c) {
                cp16(sa[buf] + c * 16, Aptr + k0 + c * 4);
                cp16(sw[buf] + c * 16, Wptr + k0 + c * 4);
            }
            cp_commit();
        }
        const float* Ab = &smem[(cur * 128) * PPAD];
        const float* Wb = &smem[((3 + cur) * 128) * PPAD];
#pragma unroll
        for (int ks = 0; ks < 4; ++ks) {
            const int k = ks * 8;
            unsigned af[4][4];
#pragma unroll
            for (int mt = 0; mt < 4; ++mt) {
                const float* a0 = Ab + (wm + mt * 16 + g) * PPAD + k + t4;
                const float* a1 = a0 + 8 * PPAD;
                af[mt][0] = f2tf(a0[0]); af[mt][1] = f2tf(a1[0]);
                af[mt][2] = f2tf(a0[4]); af[mt][3] = f2tf(a1[4]);
            }
            unsigned bf[4][2];
#pragma unroll
            for (int nt = 0; nt < 4; ++nt) {
                const float* w0 = Wb + (wn + nt * 8 + g) * PPAD + k + t4;
                bf[nt][0] = f2tf(w0[0]); bf[nt][1] = f2tf(w0[4]);
            }
#pragma unroll
            for (int mt = 0; mt < 4; ++mt)
#pragma unroll
            for (int nt = 0; nt < 4; ++nt)
                mma8(acc[mt][nt], af[mt], bf[nt]);
        }
        cur = (cur + 1 >= 3) ? 0 : cur + 1;
    }
    epi_store<EPI>(acc, bias, lng, lnb, addv, resid, rstride, out, ostride, m0, M);
}

// ---------------- Kernels ----------------

__global__ __launch_bounds__(256, 2) void k_g_spatial(
    const float* __restrict__ X, const float* __restrict__ W,
    const float* __restrict__ pb, const float* __restrict__ lng,
    const float* __restrict__ lnb, const float* __restrict__ mod, int M)
{
    pipe_gemm<2>(X, 1280, W, 1280, pb, lng, lnb, mod, nullptr, 0,
                 g_P, 384, blockIdx.x * 128, M);
}

__global__ __launch_bounds__(256, 2) void k_g_ffn2(
    const float* __restrict__ W2, const float* __restrict__ B2,
    const float* __restrict__ fg, const float* __restrict__ fb, int M)
{
    const int n = blockIdx.y;
    pipe_gemm<3>(g_h + n * 256, 768, W2 + n * 128 * 256, 256,
                 B2 + n * 128, fg + n * 128, fb + n * 128, nullptr,
                 g_x1 + n * 128, 384, g_x2 + n * 128, 384, blockIdx.x * 128, M);
}

__global__ __launch_bounds__(256) void k_g_gf(
    const float* __restrict__ Xg, const float* __restrict__ Xf,
    const float* __restrict__ Wgf, const float* __restrict__ pb,
    const float* __restrict__ lng, const float* __restrict__ lnb,
    const float* __restrict__ mod, int M)
{
    extern __shared__ float smem[];
    unsigned* As = (unsigned*)smem;
    float* Wb0 = smem + 128 * RPAD;
    const int s = blockIdx.y, n = s + 1, m0 = blockIdx.x * 128;
    const int tid = threadIdx.x, wid = tid >> 5, lane = tid & 31;
    const int wm = (wid & 1) * 64, wn = (wid >> 1) * 32, g = lane >> 2, t4 = lane & 3;

    stage_A_tf32(s ? Xf : Xg, 128, m0, M, As);
    stage_W_async(Wgf + s * 128 * 128, Wb0); cp_commit();
    cp_wait<0>(); __syncthreads();
    float acc[4][4][4] = {};
    resident_mainloop(As, Wb0, wm, wn, g, t4, acc);
    epi_store<2>(acc, pb + n * 128, lng + n * 128, lnb + n * 128, mod + n * 128,
                 nullptr, 0, g_P + n * 128, 384, m0, M);
}

__global__ __launch_bounds__(256) void k_g_qkv(
    const float* __restrict__ Wi, const float* __restrict__ Bi, int M)
{
    extern __shared__ float smem[];
    unsigned* As = (unsigned*)smem;
    float* Wb0 = smem + 128 * RPAD;
    float* Wb1 = Wb0 + 128 * RPAD;
    const int s = blockIdx.y, m0 = blockIdx.x * 128;
    const int tid = threadIdx.x, wid = tid >> 5, lane = tid & 31;
    const int wm = (wid & 1) * 64, wn = (wid >> 1) * 32, g = lane >> 2, t4 = lane & 3;

    stage_A_tf32(g_P + s * 128, 384, m0, M, As);
    stage_W_async(Wi + qkv_jobs[s][0][0], Wb0); cp_commit();
#pragma unroll 1
    for (int j = 0; j < 5; ++j) {
        cp_wait<0>();
        __syncthreads();
        if (j + 1 < 5) {
            stage_W_async(Wi + qkv_jobs[s][j + 1][0], (j & 1) ? Wb0 : Wb1);
            cp_commit();
        }
        float acc[4][4][4] = {};
        resident_mainloop(As, (j & 1) ? Wb1 : Wb0, wm, wn, g, t4, acc);
        const int bid  = qkv_jobs[s][j][2];
        const int ooff = qkv_jobs[s][j][3];
        float* obuf = (bid == 0) ? g_q + ooff : (bid == 1) ? g_k + ooff : g_v + ooff;
        epi_store<0>(acc, Bi + qkv_jobs[s][j][1], nullptr, nullptr, nullptr, nullptr, 0,
                     obuf, bid == 0 ? 384 : 768, m0, M);
    }
}

__global__ __launch_bounds__(256) void k_g_outproj(
    const float* __restrict__ Wo, const float* __restrict__ bo,
    const float* __restrict__ ag, const float* __restrict__ ab, int M)
{
    extern __shared__ float smem[];
    unsigned* As = (unsigned*)smem;
    float* Wb0 = smem + 128 * RPAD;
    const int n = blockIdx.y, m0 = blockIdx.x * 128;
    const int tid = threadIdx.x, wid = tid >> 5, lane = tid & 31;
    const int wm = (wid & 1) * 64, wn = (wid >> 1) * 32, g = lane >> 2, t4 = lane & 3;

    stage_A_tf32(g_o + n * 128, 384, m0, M, As);
    stage_W_async(Wo + n * 128 * 128, Wb0); cp_commit();
    cp_wait<0>(); __syncthreads();
    float acc[4][4][4] = {};
    resident_mainloop(As, Wb0, wm, wn, g, t4, acc);
    epi_store<3>(acc, bo + n * 128, ag + n * 128, ab + n * 128, nullptr,
                 g_P + n * 128, 384, g_x1 + n * 128, 384, m0, M);
}

__global__ __launch_bounds__(256) void k_g_ffn1(
    const float* __restrict__ W1, const float* __restrict__ B1, int M)
{
    extern __shared__ float smem[];
    unsigned* As = (unsigned*)smem;
    float* Wb0 = smem + 128 * RPAD;
    float* Wb1 = Wb0 + 128 * RPAD;
    const int n = blockIdx.y, m0 = blockIdx.x * 128;
    const int tid = threadIdx.x, wid = tid >> 5, lane = tid & 31;
    const int wm = (wid & 1) * 64, wn = (wid >> 1) * 32, g = lane >> 2, t4 = lane & 3;

    stage_A_tf32(g_x1 + n * 128, 384, m0, M, As);
    stage_W_async(W1 + n * 256 * 128, Wb0); cp_commit();
#pragma unroll 1
    for (int tl = 0; tl < 2; ++tl) {
        cp_wait<0>();
        __syncthreads();
        if (tl == 0) { stage_W_async(W1 + n * 256 * 128 + 128 * 128, Wb1); cp_commit(); }
        float acc[4][4][4] = {};
        resident_mainloop(As, tl ? Wb1 : Wb0, wm, wn, g, t4, acc);
        epi_store<1>(acc, B1 + n * 256 + tl * 128, nullptr, nullptr, nullptr, nullptr, 0,
                     g_h + n * 256 + tl * 128, 768, m0, M);
    }
}

// ---------------- Attention (float4 + octet reduce) ----------------

__global__ __launch_bounds__(256) void k_attn(int M)
{
    const int rid = blockIdx.x * 8 + (threadIdx.x >> 5);
    if (rid >= M * 3) return;
    const int lane = threadIdx.x & 31;
    const int d4 = lane * 4;
    const long qb = (long)rid * 128;
    const long kb = (long)rid * 256;

    const float4 q4  = *(const float4*)(g_q + qb + d4);
    const float4 k04 = *(const float4*)(g_k + kb + d4);
    const float4 k14 = *(const float4*)(g_k + kb + 128 + d4);
    const float4 v04 = *(const float4*)(g_v + kb + d4);
    const float4 v14 = *(const float4*)(g_v + kb + 128 + d4);

    float s0 = q4.x * k04.x + q4.y * k04.y + q4.z * k04.z + q4.w * k04.w;
    float s1 = q4.x * k14.x + q4.y * k14.y + q4.z * k14.z + q4.w * k14.w;
#pragma unroll
    for (int o = 4; o; o >>= 1) {
        s0 += __shfl_xor_sync(0xffffffffu, s0, o);
        s1 += __shfl_xor_sync(0xffffffffu, s1, o);
    }
    const float scale = 0.17677669529663687f;
    s0 *= scale; s1 *= scale;
    const float mx = fmaxf(s0, s1);
    const float e0 = expf(s0 - mx), e1 = expf(s1 - mx);
    const float inv = 1.0f / (e0 + e1);
    const float w0 = e0 * inv, w1 = e1 * inv;

    float4 o4;
    o4.x = w0 * v04.x + w1 * v14.x;
    o4.y = w0 * v04.y + w1 * v14.y;
    o4.z = w0 * v04.z + w1 * v14.z;
    o4.w = w0 * v04.w + w1 * v14.w;
    *(float4*)(g_o + qb + d4) = o4;
}

__global__ __launch_bounds__(256) void k_gate(
    const float* __restrict__ gw, const float* __restrict__ gb,
    float* __restrict__ out, int M)
{
    const int b = blockIdx.x * 8 + (threadIdx.x >> 5);
    if (b >= M) return;
    const int lane = threadIdx.x & 31;
    const float* xr = g_x2 + (long)b * 384;
    float l0 = 0.f, l1 = 0.f, l2 = 0.f;
#pragma unroll
    for (int j = 0; j < 12; ++j) {
        const int idx = lane + 32 * j;
        const float x = xr[idx];
        l0 += x * gw[idx];
        l1 += x * gw[384 + idx];
        l2 += x * gw[768 + idx];
    }
#pragma unroll
    for (int o = 16; o; o >>= 1) {
        l0 += __shfl_xor_sync(0xffffffffu, l0, o);
        l1 += __shfl_xor_sync(0xffffffffu, l1, o);
        l2 += __shfl_xor_sync(0xffffffffu, l2, o);
    }
    l0 += gb[0]; l1 += gb[1]; l2 += gb[2];
    const float mx = fmaxf(l0, fmaxf(l1, l2));
    const float e0 = expf(l0 - mx), e1 = expf(l1 - mx), e2 = expf(l2 - mx);
    const float inv = 1.0f / (e0 + e1 + e2);
    const float w0 = e0 * inv, w1 = e1 * inv, w2 = e2 * inv;
#pragma unroll
    for (int j = 0; j < 4; ++j) {
        const int d = lane + 32 * j;
        out[(long)b * 128 + d] = w0 * xr[d] + w1 * xr[128 + d] + w2 * xr[256 + d];
    }
}

// ---------------------------------------------------------------------------

extern "C" void kernel_launch(void* const* d_in, const int* in_sizes, int n_in,
                              void* d_out, int out_size)
{
    const float* x_spatial   = (const float*)d_in[0];
    const float* x_gradient  = (const float*)d_in[1];
    const float* x_frequency = (const float*)d_in[2];
    const float* w_spatial   = (const float*)d_in[3];
    const float* w_gf        = (const float*)d_in[4];
    const float* proj_b      = (const float*)d_in[5];
    const float* proj_ln_g   = (const float*)d_in[6];
    const float* proj_ln_b   = (const float*)d_in[7];
    const float* mod_emb     = (const float*)d_in[8];
    const float* in_w        = (const float*)d_in[9];
    const float* in_b        = (const float*)d_in[10];
    const float* out_w       = (const float*)d_in[11];
    const float* out_b       = (const float*)d_in[12];
    const float* attn_g      = (const float*)d_in[13];
    const float* attn_b      = (const float*)d_in[14];
    const float* w1          = (const float*)d_in[15];
    const float* b1          = (const float*)d_in[16];
    const float* w2          = (const float*)d_in[17];
    const float* b2          = (const float*)d_in[18];
    const float* ffn_g       = (const float*)d_in[19];
    const float* ffn_b       = (const float*)d_in[20];
    const float* gate_w      = (const float*)d_in[21];
    const float* gate_b      = (const float*)d_in[22];
    float* out = (float*)d_out;

    static int smem_set = 0;
    if (!smem_set) {
        cudaFuncSetAttribute(k_g_spatial, cudaFuncAttributeMaxDynamicSharedMemorySize, PSMEM);
        cudaFuncSetAttribute(k_g_ffn2,    cudaFuncAttributeMaxDynamicSharedMemorySize, PSMEM);
        cudaFuncSetAttribute(k_g_gf,      cudaFuncAttributeMaxDynamicSharedMemorySize, RSMEM);
        cudaFuncSetAttribute(k_g_qkv,     cudaFuncAttributeMaxDynamicSharedMemorySize, RSMEM);
        cudaFuncSetAttribute(k_g_outproj, cudaFuncAttributeMaxDynamicSharedMemorySize, RSMEM);
        cudaFuncSetAttribute(k_g_ffn1,    cudaFuncAttributeMaxDynamicSharedMemorySize, RSMEM);
        smem_set = 1;
    }

    int B = in_sizes[0] / 1280;
    if (B > MAXB) B = MAXB;
    const int gm = (B + 127) / 128;
    const int R  = B * 3;

    k_g_spatial<<<gm, 256, PSMEM>>>(x_spatial, w_spatial, proj_b,
                                    proj_ln_g, proj_ln_b, mod_emb, B);
    k_g_gf<<<dim3(gm, 2), 256, RSMEM>>>(x_gradient, x_frequency, w_gf, proj_b,
                                        proj_ln_g, proj_ln_b, mod_emb, B);
    k_g_qkv<<<dim3(gm, 3), 256, RSMEM>>>(in_w, in_b, B);
    k_attn<<<(R + 7) / 8, 256>>>(B);
    k_g_outproj<<<dim3(gm, 3), 256, RSMEM>>>(out_w, out_b, attn_g, attn_b, B);
    k_g_ffn1<<<dim3(gm, 3), 256, RSMEM>>>(w1, b1, B);
    k_g_ffn2<<<dim3(gm, 3), 256, PSMEM>>>(w2, b2, ffn_g, ffn_b, B);
    k_gate<<<(B + 7) / 8, 256>>>(gate_w, gate_b, out, B);
}

// round 6
// speedup vs baseline: 1.1889x; 1.1889x over previous
#include <cuda_runtime.h>
#include <math.h>

// ---------------------------------------------------------------------------
// CMAF fused block, round 6 = round 4 GEMM core (3-stage BK=16 cp.async,
// 61.4KB dyn smem, 2 CTAs/SM) + LN epilogues fused into spatial/outproj/ffn2.
// ---------------------------------------------------------------------------

#define MAXB 65536
#define GSMEM (3 * 2 * 128 * 20 * 4)   // 61440 bytes

__device__ __align__(16) float g_P [MAXB * 3 * 128];
__device__ __align__(16) float g_q [MAXB * 3 * 128];
__device__ __align__(16) float g_k [MAXB * 6 * 128];
__device__ __align__(16) float g_v [MAXB * 6 * 128];
__device__ __align__(16) float g_o [MAXB * 3 * 128];
__device__ __align__(16) float g_x1[MAXB * 3 * 128];
__device__ __align__(16) float g_h [MAXB * 3 * 256];
__device__ __align__(16) float g_x2[MAXB * 3 * 128];

// QKV jobs per source stream s: {w_off, b_off, buf_id, out_off}
__constant__ int qkv_jobs[3][5][4] = {
    { {     0,    0, 0,   0}, { 65536,  512, 1, 256}, { 81920,  640, 2, 256},
      {114688,  896, 1, 512}, {131072, 1024, 2, 512} },
    { { 49152,  384, 0, 128}, { 16384,  128, 1,   0}, { 32768,  256, 2,   0},
      {114688,  896, 1, 640}, {131072, 1024, 2, 640} },
    { { 98304,  768, 0, 256}, { 16384,  128, 1, 128}, { 32768,  256, 2, 128},
      { 65536,  512, 1, 384}, { 81920,  640, 2, 384} },
};

__device__ __forceinline__ unsigned f2tf(float f) {
    unsigned u;
    asm("cvt.rna.tf32.f32 %0, %1;" : "=r"(u) : "f"(f));
    return u;
}

__device__ __forceinline__ void mma8(float c[4], const unsigned a[4], const unsigned b[2]) {
    asm volatile(
        "mma.sync.aligned.m16n8k8.row.col.f32.tf32.tf32.f32 "
        "{%0,%1,%2,%3}, {%4,%5,%6,%7}, {%8,%9}, {%0,%1,%2,%3};\n"
        : "+f"(c[0]), "+f"(c[1]), "+f"(c[2]), "+f"(c[3])
        : "r"(a[0]), "r"(a[1]), "r"(a[2]), "r"(a[3]), "r"(b[0]), "r"(b[1]));
}

__device__ __forceinline__ void cp16(unsigned smem_dst, const void* gsrc) {
    asm volatile("cp.async.cg.shared.global [%0], [%1], 16;\n"
                 :: "r"(smem_dst), "l"(gsrc));
}
__device__ __forceinline__ void cp_commit() {
    asm volatile("cp.async.commit_group;\n");
}
template <int N>
__device__ __forceinline__ void cp_wait() {
    asm volatile("cp.async.wait_group %0;\n" :: "n"(N));
}

#define AS_IDX(s, r, c) (((s) * 128 + (r)) * 20 + (c))
#define WS_IDX(s, r, c) (3 * 128 * 20 + ((s) * 128 + (r)) * 20 + (c))

// ---------------------------------------------------------------------------
// Epilogue. EPI: 0=bias, 1=bias+gelu, 2=bias+LN+addv, 3=bias+resid+LN
// 8 warps 2(m)x4(n), warp tile 64x32.
// ---------------------------------------------------------------------------
template <int EPI>
__device__ __forceinline__ void epi_store(
    float acc[4][4][4],
    const float* __restrict__ bias,
    const float* __restrict__ lng, const float* __restrict__ lnb,
    const float* __restrict__ addv,
    const float* __restrict__ resid, int rstride,
    float* __restrict__ out, int ostride, int m0, int M)
{
    __shared__ float2 pbuf[128][4];
    const int tid = threadIdx.x, wid = tid >> 5, lane = tid & 31;
    const int wm = (wid & 1) * 64, wn = (wid >> 1) * 32, wq = wid >> 1;
    const int g = lane >> 2, t4 = lane & 3;

    float b2[4][2];
#pragma unroll
    for (int nt = 0; nt < 4; ++nt) {
        const int col = wn + nt * 8 + t4 * 2;
        b2[nt][0] = bias[col]; b2[nt][1] = bias[col + 1];
    }

    if (EPI <= 1) {
#pragma unroll
        for (int mt = 0; mt < 4; ++mt)
#pragma unroll
        for (int hf = 0; hf < 2; ++hf) {
            const int r = m0 + wm + mt * 16 + hf * 8 + g;
            if (r < M) {
                float* orow = out + (long)r * ostride;
#pragma unroll
                for (int nt = 0; nt < 4; ++nt) {
                    const int col = wn + nt * 8 + t4 * 2;
                    float c0 = acc[mt][nt][hf * 2 + 0] + b2[nt][0];
                    float c1 = acc[mt][nt][hf * 2 + 1] + b2[nt][1];
                    if (EPI == 1) {
                        c0 = c0 * 0.5f * (1.0f + erff(c0 * 0.70710678118654752f));
                        c1 = c1 * 0.5f * (1.0f + erff(c1 * 0.70710678118654752f));
                    }
                    *(float2*)(orow + col) = make_float2(c0, c1);
                }
            }
        }
        return;
    }

    // LN path
#pragma unroll
    for (int mt = 0; mt < 4; ++mt)
#pragma unroll
    for (int hf = 0; hf < 2; ++hf) {
        const int lr = wm + mt * 16 + hf * 8 + g;
        const int r  = m0 + lr;
        float s = 0.f, s2 = 0.f;
        const float* rrow = (EPI == 3) ? resid + (long)min(r, M - 1) * rstride : (const float*)0;
#pragma unroll
        for (int nt = 0; nt < 4; ++nt) {
            const int col = wn + nt * 8 + t4 * 2;
            float c0 = acc[mt][nt][hf * 2 + 0] + b2[nt][0];
            float c1 = acc[mt][nt][hf * 2 + 1] + b2[nt][1];
            if (EPI == 3) {
                const float2 rv = *(const float2*)(rrow + col);
                c0 += rv.x; c1 += rv.y;
            }
            acc[mt][nt][hf * 2 + 0] = c0; acc[mt][nt][hf * 2 + 1] = c1;
            s += c0 + c1; s2 += c0 * c0 + c1 * c1;
        }
        s  += __shfl_xor_sync(0xffffffffu, s, 1);
        s  += __shfl_xor_sync(0xffffffffu, s, 2);
        s2 += __shfl_xor_sync(0xffffffffu, s2, 1);
        s2 += __shfl_xor_sync(0xffffffffu, s2, 2);
        if (t4 == 0) pbuf[lr][wq] = make_float2(s, s2);
    }
    __syncthreads();
#pragma unroll
    for (int mt = 0; mt < 4; ++mt)
#pragma unroll
    for (int hf = 0; hf < 2; ++hf) {
        const int lr = wm + mt * 16 + hf * 8 + g;
        const int r  = m0 + lr;
        const float2 p0 = pbuf[lr][0], p1 = pbuf[lr][1], p2 = pbuf[lr][2], p3 = pbuf[lr][3];
        const float s    = p0.x + p1.x + p2.x + p3.x;
        const float s2   = p0.y + p1.y + p2.y + p3.y;
        const float mean = s * 0.0078125f;
        const float var  = s2 * 0.0078125f - mean * mean;
        const float rs   = rsqrtf(var + 1e-5f);
        if (r < M) {
            float* orow = out + (long)r * ostride;
#pragma unroll
            for (int nt = 0; nt < 4; ++nt) {
                const int col = wn + nt * 8 + t4 * 2;
                float o0 = (acc[mt][nt][hf * 2 + 0] - mean) * rs * lng[col]     + lnb[col];
                float o1 = (acc[mt][nt][hf * 2 + 1] - mean) * rs * lng[col + 1] + lnb[col + 1];
                if (EPI == 2) { o0 += addv[col]; o1 += addv[col + 1]; }
                *(float2*)(orow + col) = make_float2(o0, o1);
            }
        }
    }
}

// ---------------------------------------------------------------------------
// R4 GEMM core: 256 thr / 8 warps, warp tile 64x32, 3-stage BK=16 cp.async.
// ---------------------------------------------------------------------------
template <int EPI>
__device__ __forceinline__ void mma_gemm(
    const float* __restrict__ A, int lda,
    const float* __restrict__ W, int K,
    const float* __restrict__ bias,
    const float* __restrict__ lng, const float* __restrict__ lnb,
    const float* __restrict__ addv,
    const float* __restrict__ resid, int rstride,
    float* __restrict__ out, int ostride,
    int m0, int M)
{
    extern __shared__ float smem[];

    __syncthreads();   // guard smem reuse across consecutive calls

    const int tid   = threadIdx.x;
    const int ldRow = tid >> 1;
    const int ldCol = (tid & 1) * 8;

    const float* Aptr = A + (long)min(m0 + ldRow, M - 1) * lda + ldCol;
    const float* Wptr = W + (long)ldRow * K + ldCol;

    unsigned sa[3], sw[3];
#pragma unroll
    for (int s = 0; s < 3; ++s) {
        sa[s] = (unsigned)__cvta_generic_to_shared(&smem[AS_IDX(s, ldRow, ldCol)]);
        sw[s] = (unsigned)__cvta_generic_to_shared(&smem[WS_IDX(s, ldRow, ldCol)]);
    }

    const int wid = tid >> 5, lane = tid & 31;
    const int wm = (wid & 1) * 64;
    const int wn = (wid >> 1) * 32;
    const int g  = lane >> 2, t4 = lane & 3;

    float acc[4][4][4] = {};

    const int ntiles = K >> 4;

#pragma unroll
    for (int p = 0; p < 2; ++p) {
        const int k0 = p << 4;
        cp16(sa[p],      Aptr + k0);
        cp16(sa[p] + 16, Aptr + k0 + 4);
        cp16(sw[p],      Wptr + k0);
        cp16(sw[p] + 16, Wptr + k0 + 4);
        cp_commit();
    }

    int cur = 0;
    for (int t = 0; t < ntiles; ++t) {
        if (t + 2 < ntiles) cp_wait<1>(); else cp_wait<0>();
        __syncthreads();

        if (t + 2 < ntiles) {
            const int buf = (cur + 2 >= 3) ? cur - 1 : cur + 2;
            const int k0 = (t + 2) << 4;
            cp16(sa[buf],      Aptr + k0);
            cp16(sa[buf] + 16, Aptr + k0 + 4);
            cp16(sw[buf],      Wptr + k0);
            cp16(sw[buf] + 16, Wptr + k0 + 4);
            cp_commit();
        }

#pragma unroll
        for (int ks = 0; ks < 16; ks += 8) {
            unsigned af[4][4];
#pragma unroll
            for (int mt = 0; mt < 4; ++mt) {
                const int r = wm + mt * 16 + g;
                af[mt][0] = f2tf(smem[AS_IDX(cur, r,     ks + t4)]);
                af[mt][1] = f2tf(smem[AS_IDX(cur, r + 8, ks + t4)]);
                af[mt][2] = f2tf(smem[AS_IDX(cur, r,     ks + t4 + 4)]);
                af[mt][3] = f2tf(smem[AS_IDX(cur, r + 8, ks + t4 + 4)]);
            }
            unsigned bf[4][2];
#pragma unroll
            for (int nt = 0; nt < 4; ++nt) {
                const int n = wn + nt * 8 + g;
                bf[nt][0] = f2tf(smem[WS_IDX(cur, n, ks + t4)]);
                bf[nt][1] = f2tf(smem[WS_IDX(cur, n, ks + t4 + 4)]);
            }
#pragma unroll
            for (int mt = 0; mt < 4; ++mt)
#pragma unroll
                for (int nt = 0; nt < 4; ++nt)
                    mma8(acc[mt][nt], af[mt], bf[nt]);
        }
        cur = (cur + 1 >= 3) ? 0 : cur + 1;
    }

    epi_store<EPI>(acc, bias, lng, lnb, addv, resid, rstride, out, ostride, m0, M);
}

// ---------------- GEMM wrappers ----------------

__global__ __launch_bounds__(256, 2) void k_g_spatial(
    const float* __restrict__ X, const float* __restrict__ W,
    const float* __restrict__ pb, const float* __restrict__ lng,
    const float* __restrict__ lnb, const float* __restrict__ mod, int M)
{
    mma_gemm<2>(X, 1280, W, 1280, pb, lng, lnb, mod, nullptr, 0,
                g_P, 384, blockIdx.x * 128, M);
}

__global__ __launch_bounds__(256, 2) void k_g_gf(
    const float* __restrict__ Xg, const float* __restrict__ Xf,
    const float* __restrict__ Wgf, const float* __restrict__ pb,
    const float* __restrict__ lng, const float* __restrict__ lnb,
    const float* __restrict__ mod, int M)
{
    const int s = blockIdx.y;     // 0->grad(n=1), 1->freq(n=2)
    const int n = s + 1;
    mma_gemm<2>(s ? Xf : Xg, 128, Wgf + s * 128 * 128, 128,
                pb + n * 128, lng + n * 128, lnb + n * 128, mod + n * 128,
                nullptr, 0, g_P + n * 128, 384, blockIdx.x * 128, M);
}

__global__ __launch_bounds__(256, 2) void k_g_qkv(
    const float* __restrict__ Wi, const float* __restrict__ Bi, int M)
{
    const int s  = blockIdx.y;
    const int m0 = blockIdx.x * 128;
    const float* A = g_P + s * 128;
    float* bufs[3] = {g_q, g_k, g_v};
#pragma unroll 1
    for (int j = 0; j < 5; ++j) {
        const int woff = qkv_jobs[s][j][0];
        const int boff = qkv_jobs[s][j][1];
        const int bid  = qkv_jobs[s][j][2];
        const int ooff = qkv_jobs[s][j][3];
        mma_gemm<0>(A, 384, Wi + woff, 128, Bi + boff,
                    nullptr, nullptr, nullptr, nullptr, 0,
                    bufs[bid] + ooff, bid == 0 ? 384 : 768, m0, M);
    }
}

__global__ __launch_bounds__(256, 2) void k_g_outproj(
    const float* __restrict__ Wo, const float* __restrict__ bo,
    const float* __restrict__ ag, const float* __restrict__ ab, int M)
{
    const int n = blockIdx.y;
    mma_gemm<3>(g_o + n * 128, 384, Wo + n * 128 * 128, 128,
                bo + n * 128, ag + n * 128, ab + n * 128, nullptr,
                g_P + n * 128, 384, g_x1 + n * 128, 384, blockIdx.x * 128, M);
}

__global__ __launch_bounds__(256, 2) void k_g_ffn1(
    const float* __restrict__ W1, const float* __restrict__ B1, int M)
{
    const int n  = blockIdx.y;
    const int m0 = blockIdx.x * 128;
#pragma unroll 1
    for (int tl = 0; tl < 2; ++tl)
        mma_gemm<1>(g_x1 + n * 128, 384,
                    W1 + n * 256 * 128 + tl * 128 * 128, 128,
                    B1 + n * 256 + tl * 128,
                    nullptr, nullptr, nullptr, nullptr, 0,
                    g_h + n * 256 + tl * 128, 768, m0, M);
}

__global__ __launch_bounds__(256, 2) void k_g_ffn2(
    const float* __restrict__ W2, const float* __restrict__ B2,
    const float* __restrict__ fg, const float* __restrict__ fb, int M)
{
    const int n = blockIdx.y;
    mma_gemm<3>(g_h + n * 256, 768, W2 + n * 128 * 256, 256,
                B2 + n * 128, fg + n * 128, fb + n * 128, nullptr,
                g_x1 + n * 128, 384, g_x2 + n * 128, 384, blockIdx.x * 128, M);
}

// ---------------- Attention (float4 + octet reduce) ----------------

__global__ __launch_bounds__(256) void k_attn(int M)
{
    const int rid = blockIdx.x * 8 + (threadIdx.x >> 5);
    if (rid >= M * 3) return;
    const int lane = threadIdx.x & 31;
    const int d4 = lane * 4;
    const long qb = (long)rid * 128;
    const long kb = (long)rid * 256;

    const float4 q4  = *(const float4*)(g_q + qb + d4);
    const float4 k04 = *(const float4*)(g_k + kb + d4);
    const float4 k14 = *(const float4*)(g_k + kb + 128 + d4);
    const float4 v04 = *(const float4*)(g_v + kb + d4);
    const float4 v14 = *(const float4*)(g_v + kb + 128 + d4);

    float s0 = q4.x * k04.x + q4.y * k04.y + q4.z * k04.z + q4.w * k04.w;
    float s1 = q4.x * k14.x + q4.y * k14.y + q4.z * k14.z + q4.w * k14.w;
#pragma unroll
    for (int o = 4; o; o >>= 1) {
        s0 += __shfl_xor_sync(0xffffffffu, s0, o);
        s1 += __shfl_xor_sync(0xffffffffu, s1, o);
    }
    const float scale = 0.17677669529663687f;
    s0 *= scale; s1 *= scale;
    const float mx = fmaxf(s0, s1);
    const float e0 = expf(s0 - mx), e1 = expf(s1 - mx);
    const float inv = 1.0f / (e0 + e1);
    const float w0 = e0 * inv, w1 = e1 * inv;

    float4 o4;
    o4.x = w0 * v04.x + w1 * v14.x;
    o4.y = w0 * v04.y + w1 * v14.y;
    o4.z = w0 * v04.z + w1 * v14.z;
    o4.w = w0 * v04.w + w1 * v14.w;
    *(float4*)(g_o + qb + d4) = o4;
}

__global__ __launch_bounds__(256) void k_gate(
    const float* __restrict__ gw, const float* __restrict__ gb,
    float* __restrict__ out, int M)
{
    const int b = blockIdx.x * 8 + (threadIdx.x >> 5);
    if (b >= M) return;
    const int lane = threadIdx.x & 31;
    const float* xr = g_x2 + (long)b * 384;
    float l0 = 0.f, l1 = 0.f, l2 = 0.f;
#pragma unroll
    for (int j = 0; j < 12; ++j) {
        const int idx = lane + 32 * j;
        const float x = xr[idx];
        l0 += x * gw[idx];
        l1 += x * gw[384 + idx];
        l2 += x * gw[768 + idx];
    }
#pragma unroll
    for (int o = 16; o; o >>= 1) {
        l0 += __shfl_xor_sync(0xffffffffu, l0, o);
        l1 += __shfl_xor_sync(0xffffffffu, l1, o);
        l2 += __shfl_xor_sync(0xffffffffu, l2, o);
    }
    l0 += gb[0]; l1 += gb[1]; l2 += gb[2];
    const float mx = fmaxf(l0, fmaxf(l1, l2));
    const float e0 = expf(l0 - mx), e1 = expf(l1 - mx), e2 = expf(l2 - mx);
    const float inv = 1.0f / (e0 + e1 + e2);
    const float w0 = e0 * inv, w1 = e1 * inv, w2 = e2 * inv;
#pragma unroll
    for (int j = 0; j < 4; ++j) {
        const int d = lane + 32 * j;
        out[(long)b * 128 + d] = w0 * xr[d] + w1 * xr[128 + d] + w2 * xr[256 + d];
    }
}

// ---------------------------------------------------------------------------

extern "C" void kernel_launch(void* const* d_in, const int* in_sizes, int n_in,
                              void* d_out, int out_size)
{
    const float* x_spatial   = (const float*)d_in[0];
    const float* x_gradient  = (const float*)d_in[1];
    const float* x_frequency = (const float*)d_in[2];
    const float* w_spatial   = (const float*)d_in[3];
    const float* w_gf        = (const float*)d_in[4];
    const float* proj_b      = (const float*)d_in[5];
    const float* proj_ln_g   = (const float*)d_in[6];
    const float* proj_ln_b   = (const float*)d_in[7];
    const float* mod_emb     = (const float*)d_in[8];
    const float* in_w        = (const float*)d_in[9];
    const float* in_b        = (const float*)d_in[10];
    const float* out_w       = (const float*)d_in[11];
    const float* out_b       = (const float*)d_in[12];
    const float* attn_g      = (const float*)d_in[13];
    const float* attn_b      = (const float*)d_in[14];
    const float* w1          = (const float*)d_in[15];
    const float* b1          = (const float*)d_in[16];
    const float* w2          = (const float*)d_in[17];
    const float* b2          = (const float*)d_in[18];
    const float* ffn_g       = (const float*)d_in[19];
    const float* ffn_b       = (const float*)d_in[20];
    const float* gate_w      = (const float*)d_in[21];
    const float* gate_b      = (const float*)d_in[22];
    float* out = (float*)d_out;

    static int smem_set = 0;
    if (!smem_set) {
        cudaFuncSetAttribute(k_g_spatial, cudaFuncAttributeMaxDynamicSharedMemorySize, GSMEM);
        cudaFuncSetAttribute(k_g_gf,      cudaFuncAttributeMaxDynamicSharedMemorySize, GSMEM);
        cudaFuncSetAttribute(k_g_qkv,     cudaFuncAttributeMaxDynamicSharedMemorySize, GSMEM);
        cudaFuncSetAttribute(k_g_outproj, cudaFuncAttributeMaxDynamicSharedMemorySize, GSMEM);
        cudaFuncSetAttribute(k_g_ffn1,    cudaFuncAttributeMaxDynamicSharedMemorySize, GSMEM);
        cudaFuncSetAttribute(k_g_ffn2,    cudaFuncAttributeMaxDynamicSharedMemorySize, GSMEM);
        smem_set = 1;
    }

    int B = in_sizes[0] / 1280;
    if (B > MAXB) B = MAXB;
    const int gm = (B + 127) / 128;
    const int R  = B * 3;

    k_g_spatial<<<gm, 256, GSMEM>>>(x_spatial, w_spatial, proj_b,
                                    proj_ln_g, proj_ln_b, mod_emb, B);
    k_g_gf<<<dim3(gm, 2), 256, GSMEM>>>(x_gradient, x_frequency, w_gf, proj_b,
                                        proj_ln_g, proj_ln_b, mod_emb, B);
    k_g_qkv<<<dim3(gm, 3), 256, GSMEM>>>(in_w, in_b, B);
    k_attn<<<(R + 7) / 8, 256>>>(B);
    k_g_outproj<<<dim3(gm, 3), 256, GSMEM>>>(out_w, out_b, attn_g, attn_b, B);
    k_g_ffn1<<<dim3(gm, 3), 256, GSMEM>>>(w1, b1, B);
    k_g_ffn2<<<dim3(gm, 3), 256, GSMEM>>>(w2, b2, ffn_g, ffn_b, B);
    k_gate<<<(B + 7) / 8, 256>>>(gate_w, gate_b, out, B);
}

// round 7
// speedup vs baseline: 1.2464x; 1.0484x over previous
#include <cuda_runtime.h>
#include <math.h>

// ---------------------------------------------------------------------------
// CMAF fused block, round 7 = round 6 + CVT elimination:
//   - all weights pre-converted to tf32 scratch once per launch
//   - GEMM-feeding activations stored tf32-rounded at producing epilogue
//   - mainloop fragment loads are raw bit loads (no cvt) except spatial/gf A
// ---------------------------------------------------------------------------

#define MAXB 65536
#define GSMEM (3 * 2 * 128 * 20 * 4)   // 61440 bytes

__device__ __align__(16) float g_P [MAXB * 3 * 128];
__device__ __align__(16) float g_q [MAXB * 3 * 128];
__device__ __align__(16) float g_k [MAXB * 6 * 128];
__device__ __align__(16) float g_v [MAXB * 6 * 128];
__device__ __align__(16) float g_o [MAXB * 3 * 128];
__device__ __align__(16) float g_x1[MAXB * 3 * 128];
__device__ __align__(16) float g_h [MAXB * 3 * 256];
__device__ __align__(16) float g_x2[MAXB * 3 * 128];

// tf32-preconverted weights
#define WOFF_SPATIAL 0
#define WOFF_GF      163840
#define WOFF_INW     196608
#define WOFF_OUTW    344064
#define WOFF_FFN1    393216
#define WOFF_FFN2    491520
__device__ __align__(16) float g_wtf[589824];

// QKV jobs per source stream s: {w_off (within in_w), b_off, buf_id, out_off}
__constant__ int qkv_jobs[3][5][4] = {
    { {     0,    0, 0,   0}, { 65536,  512, 1, 256}, { 81920,  640, 2, 256},
      {114688,  896, 1, 512}, {131072, 1024, 2, 512} },
    { { 49152,  384, 0, 128}, { 16384,  128, 1,   0}, { 32768,  256, 2,   0},
      {114688,  896, 1, 640}, {131072, 1024, 2, 640} },
    { { 98304,  768, 0, 256}, { 16384,  128, 1, 128}, { 32768,  256, 2, 128},
      { 65536,  512, 1, 384}, { 81920,  640, 2, 384} },
};

__device__ __forceinline__ unsigned f2tf(float f) {
    unsigned u;
    asm("cvt.rna.tf32.f32 %0, %1;" : "=r"(u) : "f"(f));
    return u;
}
__device__ __forceinline__ float tfr(float f) {   // round-to-tf32, as float
    return __uint_as_float(f2tf(f));
}

__device__ __forceinline__ void mma8(float c[4], const unsigned a[4], const unsigned b[2]) {
    asm volatile(
        "mma.sync.aligned.m16n8k8.row.col.f32.tf32.tf32.f32 "
        "{%0,%1,%2,%3}, {%4,%5,%6,%7}, {%8,%9}, {%0,%1,%2,%3};\n"
        : "+f"(c[0]), "+f"(c[1]), "+f"(c[2]), "+f"(c[3])
        : "r"(a[0]), "r"(a[1]), "r"(a[2]), "r"(a[3]), "r"(b[0]), "r"(b[1]));
}

__device__ __forceinline__ void cp16(unsigned smem_dst, const void* gsrc) {
    asm volatile("cp.async.cg.shared.global [%0], [%1], 16;\n"
                 :: "r"(smem_dst), "l"(gsrc));
}
__device__ __forceinline__ void cp_commit() {
    asm volatile("cp.async.commit_group;\n");
}
template <int N>
__device__ __forceinline__ void cp_wait() {
    asm volatile("cp.async.wait_group %0;\n" :: "n"(N));
}

#define AS_IDX(s, r, c) (((s) * 128 + (r)) * 20 + (c))
#define WS_IDX(s, r, c) (3 * 128 * 20 + ((s) * 128 + (r)) * 20 + (c))

// ---------------- weight tf32 pre-convert ----------------
__global__ __launch_bounds__(256) void k_cvt(
    const float* __restrict__ src, float* __restrict__ dst, int n4)
{
    const int i = blockIdx.x * 256 + threadIdx.x;
    if (i < n4) {
        const float4 v = *(const float4*)(src + 4 * i);
        float4 o;
        o.x = tfr(v.x); o.y = tfr(v.y); o.z = tfr(v.z); o.w = tfr(v.w);
        *(float4*)(dst + 4 * i) = o;
    }
}

// ---------------------------------------------------------------------------
// Epilogue. EPI: 0=bias, 1=bias+gelu, 2=bias+LN+addv, 3=bias+resid+LN
// RND: store tf32-rounded (output feeds a later GEMM as A)
// ---------------------------------------------------------------------------
template <int EPI, int RND>
__device__ __forceinline__ void epi_store(
    float acc[4][4][4],
    const float* __restrict__ bias,
    const float* __restrict__ lng, const float* __restrict__ lnb,
    const float* __restrict__ addv,
    const float* __restrict__ resid, int rstride,
    float* __restrict__ out, int ostride, int m0, int M)
{
    __shared__ float2 pbuf[128][4];
    const int tid = threadIdx.x, wid = tid >> 5, lane = tid & 31;
    const int wm = (wid & 1) * 64, wn = (wid >> 1) * 32, wq = wid >> 1;
    const int g = lane >> 2, t4 = lane & 3;

    float b2[4][2];
#pragma unroll
    for (int nt = 0; nt < 4; ++nt) {
        const int col = wn + nt * 8 + t4 * 2;
        b2[nt][0] = bias[col]; b2[nt][1] = bias[col + 1];
    }

    if (EPI <= 1) {
#pragma unroll
        for (int mt = 0; mt < 4; ++mt)
#pragma unroll
        for (int hf = 0; hf < 2; ++hf) {
            const int r = m0 + wm + mt * 16 + hf * 8 + g;
            if (r < M) {
                float* orow = out + (long)r * ostride;
#pragma unroll
                for (int nt = 0; nt < 4; ++nt) {
                    const int col = wn + nt * 8 + t4 * 2;
                    float c0 = acc[mt][nt][hf * 2 + 0] + b2[nt][0];
                    float c1 = acc[mt][nt][hf * 2 + 1] + b2[nt][1];
                    if (EPI == 1) {
                        c0 = c0 * 0.5f * (1.0f + erff(c0 * 0.70710678118654752f));
                        c1 = c1 * 0.5f * (1.0f + erff(c1 * 0.70710678118654752f));
                    }
                    if (RND) { c0 = tfr(c0); c1 = tfr(c1); }
                    *(float2*)(orow + col) = make_float2(c0, c1);
                }
            }
        }
        return;
    }

    // LN path
#pragma unroll
    for (int mt = 0; mt < 4; ++mt)
#pragma unroll
    for (int hf = 0; hf < 2; ++hf) {
        const int lr = wm + mt * 16 + hf * 8 + g;
        const int r  = m0 + lr;
        float s = 0.f, s2 = 0.f;
        const float* rrow = (EPI == 3) ? resid + (long)min(r, M - 1) * rstride : (const float*)0;
#pragma unroll
        for (int nt = 0; nt < 4; ++nt) {
            const int col = wn + nt * 8 + t4 * 2;
            float c0 = acc[mt][nt][hf * 2 + 0] + b2[nt][0];
            float c1 = acc[mt][nt][hf * 2 + 1] + b2[nt][1];
            if (EPI == 3) {
                const float2 rv = *(const float2*)(rrow + col);
                c0 += rv.x; c1 += rv.y;
            }
            acc[mt][nt][hf * 2 + 0] = c0; acc[mt][nt][hf * 2 + 1] = c1;
            s += c0 + c1; s2 += c0 * c0 + c1 * c1;
        }
        s  += __shfl_xor_sync(0xffffffffu, s, 1);
        s  += __shfl_xor_sync(0xffffffffu, s, 2);
        s2 += __shfl_xor_sync(0xffffffffu, s2, 1);
        s2 += __shfl_xor_sync(0xffffffffu, s2, 2);
        if (t4 == 0) pbuf[lr][wq] = make_float2(s, s2);
    }
    __syncthreads();
#pragma unroll
    for (int mt = 0; mt < 4; ++mt)
#pragma unroll
    for (int hf = 0; hf < 2; ++hf) {
        const int lr = wm + mt * 16 + hf * 8 + g;
        const int r  = m0 + lr;
        const float2 p0 = pbuf[lr][0], p1 = pbuf[lr][1], p2 = pbuf[lr][2], p3 = pbuf[lr][3];
        const float s    = p0.x + p1.x + p2.x + p3.x;
        const float s2   = p0.y + p1.y + p2.y + p3.y;
        const float mean = s * 0.0078125f;
        const float var  = s2 * 0.0078125f - mean * mean;
        const float rs   = rsqrtf(var + 1e-5f);
        if (r < M) {
            float* orow = out + (long)r * ostride;
#pragma unroll
            for (int nt = 0; nt < 4; ++nt) {
                const int col = wn + nt * 8 + t4 * 2;
                float o0 = (acc[mt][nt][hf * 2 + 0] - mean) * rs * lng[col]     + lnb[col];
                float o1 = (acc[mt][nt][hf * 2 + 1] - mean) * rs * lng[col + 1] + lnb[col + 1];
                if (EPI == 2) { o0 += addv[col]; o1 += addv[col + 1]; }
                if (RND) { o0 = tfr(o0); o1 = tfr(o1); }
                *(float2*)(orow + col) = make_float2(o0, o1);
            }
        }
    }
}

// ---------------------------------------------------------------------------
// GEMM core: 256 thr / 8 warps, warp tile 64x32, 3-stage BK=16 cp.async.
// CVTA: convert A fragments (external fp32 input). B always pre-converted.
// ---------------------------------------------------------------------------
template <int EPI, int RND, int CVTA>
__device__ __forceinline__ void mma_gemm(
    const float* __restrict__ A, int lda,
    const float* __restrict__ W, int K,
    const float* __restrict__ bias,
    const float* __restrict__ lng, const float* __restrict__ lnb,
    const float* __restrict__ addv,
    const float* __restrict__ resid, int rstride,
    float* __restrict__ out, int ostride,
    int m0, int M)
{
    extern __shared__ float smem[];

    __syncthreads();   // guard smem reuse across consecutive calls

    const int tid   = threadIdx.x;
    const int ldRow = tid >> 1;
    const int ldCol = (tid & 1) * 8;

    const float* Aptr = A + (long)min(m0 + ldRow, M - 1) * lda + ldCol;
    const float* Wptr = W + (long)ldRow * K + ldCol;

    unsigned sa[3], sw[3];
#pragma unroll
    for (int s = 0; s < 3; ++s) {
        sa[s] = (unsigned)__cvta_generic_to_shared(&smem[AS_IDX(s, ldRow, ldCol)]);
        sw[s] = (unsigned)__cvta_generic_to_shared(&smem[WS_IDX(s, ldRow, ldCol)]);
    }

    const int wid = tid >> 5, lane = tid & 31;
    const int wm = (wid & 1) * 64;
    const int wn = (wid >> 1) * 32;
    const int g  = lane >> 2, t4 = lane & 3;

    float acc[4][4][4] = {};

    const int ntiles = K >> 4;

#pragma unroll
    for (int p = 0; p < 2; ++p) {
        const int k0 = p << 4;
        cp16(sa[p],      Aptr + k0);
        cp16(sa[p] + 16, Aptr + k0 + 4);
        cp16(sw[p],      Wptr + k0);
        cp16(sw[p] + 16, Wptr + k0 + 4);
        cp_commit();
    }

    int cur = 0;
    for (int t = 0; t < ntiles; ++t) {
        if (t + 2 < ntiles) cp_wait<1>(); else cp_wait<0>();
        __syncthreads();

        if (t + 2 < ntiles) {
            const int buf = (cur + 2 >= 3) ? cur - 1 : cur + 2;
            const int k0 = (t + 2) << 4;
            cp16(sa[buf],      Aptr + k0);
            cp16(sa[buf] + 16, Aptr + k0 + 4);
            cp16(sw[buf],      Wptr + k0);
            cp16(sw[buf] + 16, Wptr + k0 + 4);
            cp_commit();
        }

#pragma unroll
        for (int ks = 0; ks < 16; ks += 8) {
            unsigned af[4][4];
#pragma unroll
            for (int mt = 0; mt < 4; ++mt) {
                const int r = wm + mt * 16 + g;
                if (CVTA) {
                    af[mt][0] = f2tf(smem[AS_IDX(cur, r,     ks + t4)]);
                    af[mt][1] = f2tf(smem[AS_IDX(cur, r + 8, ks + t4)]);
                    af[mt][2] = f2tf(smem[AS_IDX(cur, r,     ks + t4 + 4)]);
                    af[mt][3] = f2tf(smem[AS_IDX(cur, r + 8, ks + t4 + 4)]);
                } else {
                    af[mt][0] = __float_as_uint(smem[AS_IDX(cur, r,     ks + t4)]);
                    af[mt][1] = __float_as_uint(smem[AS_IDX(cur, r + 8, ks + t4)]);
                    af[mt][2] = __float_as_uint(smem[AS_IDX(cur, r,     ks + t4 + 4)]);
                    af[mt][3] = __float_as_uint(smem[AS_IDX(cur, r + 8, ks + t4 + 4)]);
                }
            }
            unsigned bf[4][2];
#pragma unroll
            for (int nt = 0; nt < 4; ++nt) {
                const int n = wn + nt * 8 + g;
                bf[nt][0] = __float_as_uint(smem[WS_IDX(cur, n, ks + t4)]);
                bf[nt][1] = __float_as_uint(smem[WS_IDX(cur, n, ks + t4 + 4)]);
            }
#pragma unroll
            for (int mt = 0; mt < 4; ++mt)
#pragma unroll
                for (int nt = 0; nt < 4; ++nt)
                    mma8(acc[mt][nt], af[mt], bf[nt]);
        }
        cur = (cur + 1 >= 3) ? 0 : cur + 1;
    }

    epi_store<EPI, RND>(acc, bias, lng, lnb, addv, resid, rstride, out, ostride, m0, M);
}

// ---------------- GEMM wrappers ----------------

__global__ __launch_bounds__(256, 2) void k_g_spatial(
    const float* __restrict__ X,
    const float* __restrict__ pb, const float* __restrict__ lng,
    const float* __restrict__ lnb, const float* __restrict__ mod, int M)
{
    mma_gemm<2, 1, 1>(X, 1280, g_wtf + WOFF_SPATIAL, 1280, pb, lng, lnb, mod,
                      nullptr, 0, g_P, 384, blockIdx.x * 128, M);
}

__global__ __launch_bounds__(256, 2) void k_g_gf(
    const float* __restrict__ Xg, const float* __restrict__ Xf,
    const float* __restrict__ pb,
    const float* __restrict__ lng, const float* __restrict__ lnb,
    const float* __restrict__ mod, int M)
{
    const int s = blockIdx.y;     // 0->grad(n=1), 1->freq(n=2)
    const int n = s + 1;
    mma_gemm<2, 1, 1>(s ? Xf : Xg, 128, g_wtf + WOFF_GF + s * 128 * 128, 128,
                      pb + n * 128, lng + n * 128, lnb + n * 128, mod + n * 128,
                      nullptr, 0, g_P + n * 128, 384, blockIdx.x * 128, M);
}

__global__ __launch_bounds__(256, 2) void k_g_qkv(
    const float* __restrict__ Bi, int M)
{
    const int s  = blockIdx.y;
    const int m0 = blockIdx.x * 128;
    const float* A = g_P + s * 128;
    float* bufs[3] = {g_q, g_k, g_v};
#pragma unroll 1
    for (int j = 0; j < 5; ++j) {
        const int woff = qkv_jobs[s][j][0];
        const int boff = qkv_jobs[s][j][1];
        const int bid  = qkv_jobs[s][j][2];
        const int ooff = qkv_jobs[s][j][3];
        mma_gemm<0, 0, 0>(A, 384, g_wtf + WOFF_INW + woff, 128, Bi + boff,
                          nullptr, nullptr, nullptr, nullptr, 0,
                          bufs[bid] + ooff, bid == 0 ? 384 : 768, m0, M);
    }
}

__global__ __launch_bounds__(256, 2) void k_g_outproj(
    const float* __restrict__ bo,
    const float* __restrict__ ag, const float* __restrict__ ab, int M)
{
    const int n = blockIdx.y;
    mma_gemm<3, 1, 0>(g_o + n * 128, 384, g_wtf + WOFF_OUTW + n * 128 * 128, 128,
                      bo + n * 128, ag + n * 128, ab + n * 128, nullptr,
                      g_P + n * 128, 384, g_x1 + n * 128, 384, blockIdx.x * 128, M);
}

__global__ __launch_bounds__(256, 2) void k_g_ffn1(
    const float* __restrict__ B1, int M)
{
    const int n  = blockIdx.y;
    const int m0 = blockIdx.x * 128;
#pragma unroll 1
    for (int tl = 0; tl < 2; ++tl)
        mma_gemm<1, 1, 0>(g_x1 + n * 128, 384,
                          g_wtf + WOFF_FFN1 + n * 256 * 128 + tl * 128 * 128, 128,
                          B1 + n * 256 + tl * 128,
                          nullptr, nullptr, nullptr, nullptr, 0,
                          g_h + n * 256 + tl * 128, 768, m0, M);
}

__global__ __launch_bounds__(256, 2) void k_g_ffn2(
    const float* __restrict__ B2,
    const float* __restrict__ fg, const float* __restrict__ fb, int M)
{
    const int n = blockIdx.y;
    mma_gemm<3, 0, 0>(g_h + n * 256, 768, g_wtf + WOFF_FFN2 + n * 128 * 256, 256,
                      B2 + n * 128, fg + n * 128, fb + n * 128, nullptr,
                      g_x1 + n * 128, 384, g_x2 + n * 128, 384, blockIdx.x * 128, M);
}

// ---------------- Attention (float4 + octet reduce) ----------------

__global__ __launch_bounds__(256) void k_attn(int M)
{
    const int rid = blockIdx.x * 8 + (threadIdx.x >> 5);
    if (rid >= M * 3) return;
    const int lane = threadIdx.x & 31;
    const int d4 = lane * 4;
    const long qb = (long)rid * 128;
    const long kb = (long)rid * 256;

    const float4 q4  = *(const float4*)(g_q + qb + d4);
    const float4 k04 = *(const float4*)(g_k + kb + d4);
    const float4 k14 = *(const float4*)(g_k + kb + 128 + d4);
    const float4 v04 = *(const float4*)(g_v + kb + d4);
    const float4 v14 = *(const float4*)(g_v + kb + 128 + d4);

    float s0 = q4.x * k04.x + q4.y * k04.y + q4.z * k04.z + q4.w * k04.w;
    float s1 = q4.x * k14.x + q4.y * k14.y + q4.z * k14.z + q4.w * k14.w;
#pragma unroll
    for (int o = 4; o; o >>= 1) {
        s0 += __shfl_xor_sync(0xffffffffu, s0, o);
        s1 += __shfl_xor_sync(0xffffffffu, s1, o);
    }
    const float scale = 0.17677669529663687f;
    s0 *= scale; s1 *= scale;
    const float mx = fmaxf(s0, s1);
    const float e0 = expf(s0 - mx), e1 = expf(s1 - mx);
    const float inv = 1.0f / (e0 + e1);
    const float w0 = e0 * inv, w1 = e1 * inv;

    float4 o4;   // tf32-rounded: feeds outproj GEMM as A
    o4.x = tfr(w0 * v04.x + w1 * v14.x);
    o4.y = tfr(w0 * v04.y + w1 * v14.y);
    o4.z = tfr(w0 * v04.z + w1 * v14.z);
    o4.w = tfr(w0 * v04.w + w1 * v14.w);
    *(float4*)(g_o + qb + d4) = o4;
}

__global__ __launch_bounds__(256) void k_gate(
    const float* __restrict__ gw, const float* __restrict__ gb,
    float* __restrict__ out, int M)
{
    const int b = blockIdx.x * 8 + (threadIdx.x >> 5);
    if (b >= M) return;
    const int lane = threadIdx.x & 31;
    const float* xr = g_x2 + (long)b * 384;
    float l0 = 0.f, l1 = 0.f, l2 = 0.f;
#pragma unroll
    for (int j = 0; j < 12; ++j) {
        const int idx = lane + 32 * j;
        const float x = xr[idx];
        l0 += x * gw[idx];
        l1 += x * gw[384 + idx];
        l2 += x * gw[768 + idx];
    }
#pragma unroll
    for (int o = 16; o; o >>= 1) {
        l0 += __shfl_xor_sync(0xffffffffu, l0, o);
        l1 += __shfl_xor_sync(0xffffffffu, l1, o);
        l2 += __shfl_xor_sync(0xffffffffu, l2, o);
    }
    l0 += gb[0]; l1 += gb[1]; l2 += gb[2];
    const float mx = fmaxf(l0, fmaxf(l1, l2));
    const float e0 = expf(l0 - mx), e1 = expf(l1 - mx), e2 = expf(l2 - mx);
    const float inv = 1.0f / (e0 + e1 + e2);
    const float w0 = e0 * inv, w1 = e1 * inv, w2 = e2 * inv;
#pragma unroll
    for (int j = 0; j < 4; ++j) {
        const int d = lane + 32 * j;
        out[(long)b * 128 + d] = w0 * xr[d] + w1 * xr[128 + d] + w2 * xr[256 + d];
    }
}

// ---------------------------------------------------------------------------

extern "C" void kernel_launch(void* const* d_in, const int* in_sizes, int n_in,
                              void* d_out, int out_size)
{
    const float* x_spatial   = (const float*)d_in[0];
    const float* x_gradient  = (const float*)d_in[1];
    const float* x_frequency = (const float*)d_in[2];
    const float* w_spatial   = (const float*)d_in[3];
    const float* w_gf        = (const float*)d_in[4];
    const float* proj_b      = (const float*)d_in[5];
    const float* proj_ln_g   = (const float*)d_in[6];
    const float* proj_ln_b   = (const float*)d_in[7];
    const float* mod_emb     = (const float*)d_in[8];
    const float* in_w        = (const float*)d_in[9];
    const float* in_b        = (const float*)d_in[10];
    const float* out_w       = (const float*)d_in[11];
    const float* out_b       = (const float*)d_in[12];
    const float* attn_g      = (const float*)d_in[13];
    const float* attn_b      = (const float*)d_in[14];
    const float* w1          = (const float*)d_in[15];
    const float* b1          = (const float*)d_in[16];
    const float* w2          = (const float*)d_in[17];
    const float* b2          = (const float*)d_in[18];
    const float* ffn_g       = (const float*)d_in[19];
    const float* ffn_b       = (const float*)d_in[20];
    const float* gate_w      = (const float*)d_in[21];
    const float* gate_b      = (const float*)d_in[22];
    float* out = (float*)d_out;

    static int smem_set = 0;
    if (!smem_set) {
        cudaFuncSetAttribute(k_g_spatial, cudaFuncAttributeMaxDynamicSharedMemorySize, GSMEM);
        cudaFuncSetAttribute(k_g_gf,      cudaFuncAttributeMaxDynamicSharedMemorySize, GSMEM);
        cudaFuncSetAttribute(k_g_qkv,     cudaFuncAttributeMaxDynamicSharedMemorySize, GSMEM);
        cudaFuncSetAttribute(k_g_outproj, cudaFuncAttributeMaxDynamicSharedMemorySize, GSMEM);
        cudaFuncSetAttribute(k_g_ffn1,    cudaFuncAttributeMaxDynamicSharedMemorySize, GSMEM);
        cudaFuncSetAttribute(k_g_ffn2,    cudaFuncAttributeMaxDynamicSharedMemorySize, GSMEM);
        smem_set = 1;
    }

    int B = in_sizes[0] / 1280;
    if (B > MAXB) B = MAXB;
    const int gm = (B + 127) / 128;
    const int R  = B * 3;

    // weight pre-conversion (tiny; ~2.4MB total)
    float* wtf;
    cudaGetSymbolAddress((void**)&wtf, g_wtf);
    k_cvt<<<(163840/4 + 255)/256, 256>>>(w_spatial, wtf + WOFF_SPATIAL, 163840/4);
    k_cvt<<<( 32768/4 + 255)/256, 256>>>(w_gf,      wtf + WOFF_GF,       32768/4);
    k_cvt<<<(147456/4 + 255)/256, 256>>>(in_w,      wtf + WOFF_INW,     147456/4);
    k_cvt<<<( 49152/4 + 255)/256, 256>>>(out_w,     wtf + WOFF_OUTW,     49152/4);
    k_cvt<<<( 98304/4 + 255)/256, 256>>>(w1,        wtf + WOFF_FFN1,     98304/4);
    k_cvt<<<( 98304/4 + 255)/256, 256>>>(w2,        wtf + WOFF_FFN2,     98304/4);

    k_g_spatial<<<gm, 256, GSMEM>>>(x_spatial, proj_b, proj_ln_g, proj_ln_b, mod_emb, B);
    k_g_gf<<<dim3(gm, 2), 256, GSMEM>>>(x_gradient, x_frequency, proj_b,
                                        proj_ln_g, proj_ln_b, mod_emb, B);
    k_g_qkv<<<dim3(gm, 3), 256, GSMEM>>>(in_b, B);
    k_attn<<<(R + 7) / 8, 256>>>(B);
    k_g_outproj<<<dim3(gm, 3), 256, GSMEM>>>(out_b, attn_g, attn_b, B);
    k_g_ffn1<<<dim3(gm, 3), 256, GSMEM>>>(b1, B);
    k_g_ffn2<<<dim3(gm, 3), 256, GSMEM>>>(b2, ffn_g, ffn_b, B);
    k_gate<<<(B + 7) / 8, 256>>>(gate_w, gate_b, out, B);
}

// round 9
// speedup vs baseline: 1.3007x; 1.0435x over previous
#include <cuda_runtime.h>
#include <math.h>

// ---------------------------------------------------------------------------
// CMAF fused block, round 9 = round 7 + k-slot permutation (sigma trick):
// both mma operands take k slots {2*t4, 2*t4+1} instead of {t4, t4+4} ->
// all fragment loads become LDS.64, mainloop issue slots -30%. Pad 20->24
// keeps 64-bit loads bank-conflict-free. Math bit-identical (k-perm applied
// to both operands).
// ---------------------------------------------------------------------------

#define MAXB 65536
#define GPAD 24
#define GSMEM (3 * 2 * 128 * GPAD * 4)   // 73728 bytes

__device__ __align__(16) float g_P [MAXB * 3 * 128];
__device__ __align__(16) float g_q [MAXB * 3 * 128];
__device__ __align__(16) float g_k [MAXB * 6 * 128];
__device__ __align__(16) float g_v [MAXB * 6 * 128];
__device__ __align__(16) float g_o [MAXB * 3 * 128];
__device__ __align__(16) float g_x1[MAXB * 3 * 128];
__device__ __align__(16) float g_h [MAXB * 3 * 256];
__device__ __align__(16) float g_x2[MAXB * 3 * 128];

// tf32-preconverted weights
#define WOFF_SPATIAL 0
#define WOFF_GF      163840
#define WOFF_INW     196608
#define WOFF_OUTW    344064
#define WOFF_FFN1    393216
#define WOFF_FFN2    491520
__device__ __align__(16) float g_wtf[589824];

// QKV jobs per source stream s: {w_off (within in_w), b_off, buf_id, out_off}
__constant__ int qkv_jobs[3][5][4] = {
    { {     0,    0, 0,   0}, { 65536,  512, 1, 256}, { 81920,  640, 2, 256},
      {114688,  896, 1, 512}, {131072, 1024, 2, 512} },
    { { 49152,  384, 0, 128}, { 16384,  128, 1,   0}, { 32768,  256, 2,   0},
      {114688,  896, 1, 640}, {131072, 1024, 2, 640} },
    { { 98304,  768, 0, 256}, { 16384,  128, 1, 128}, { 32768,  256, 2, 128},
      { 65536,  512, 1, 384}, { 81920,  640, 2, 384} },
};

__device__ __forceinline__ unsigned f2tf(float f) {
    unsigned u;
    asm("cvt.rna.tf32.f32 %0, %1;" : "=r"(u) : "f"(f));
    return u;
}
__device__ __forceinline__ float tfr(float f) {
    return __uint_as_float(f2tf(f));
}

__device__ __forceinline__ void mma8(float c[4], const unsigned a[4], const unsigned b[2]) {
    asm volatile(
        "mma.sync.aligned.m16n8k8.row.col.f32.tf32.tf32.f32 "
        "{%0,%1,%2,%3}, {%4,%5,%6,%7}, {%8,%9}, {%0,%1,%2,%3};\n"
        : "+f"(c[0]), "+f"(c[1]), "+f"(c[2]), "+f"(c[3])
        : "r"(a[0]), "r"(a[1]), "r"(a[2]), "r"(a[3]), "r"(b[0]), "r"(b[1]));
}

__device__ __forceinline__ void cp16(unsigned smem_dst, const void* gsrc) {
    asm volatile("cp.async.cg.shared.global [%0], [%1], 16;\n"
                 :: "r"(smem_dst), "l"(gsrc));
}
__device__ __forceinline__ void cp_commit() {
    asm volatile("cp.async.commit_group;\n");
}
template <int N>
__device__ __forceinline__ void cp_wait() {
    asm volatile("cp.async.wait_group %0;\n" :: "n"(N));
}

#define AS_IDX(s, r, c) (((s) * 128 + (r)) * GPAD + (c))
#define WS_IDX(s, r, c) (3 * 128 * GPAD + ((s) * 128 + (r)) * GPAD + (c))

// ---------------------------------------------------------------------------
// Epilogue. EPI: 0=bias, 1=bias+gelu, 2=bias+LN+addv, 3=bias+resid+LN
// RND: store tf32-rounded (output feeds a later GEMM as A)
// ---------------------------------------------------------------------------
template <int EPI, int RND>
__device__ __forceinline__ void epi_store(
    float acc[4][4][4],
    const float* __restrict__ bias,
    const float* __restrict__ lng, const float* __restrict__ lnb,
    const float* __restrict__ addv,
    const float* __restrict__ resid, int rstride,
    float* __restrict__ out, int ostride, int m0, int M)
{
    __shared__ float2 pbuf[128][4];
    const int tid = threadIdx.x, wid = tid >> 5, lane = tid & 31;
    const int wm = (wid & 1) * 64, wn = (wid >> 1) * 32, wq = wid >> 1;
    const int g = lane >> 2, t4 = lane & 3;

    float b2[4][2];
#pragma unroll
    for (int nt = 0; nt < 4; ++nt) {
        const int col = wn + nt * 8 + t4 * 2;
        b2[nt][0] = bias[col]; b2[nt][1] = bias[col + 1];
    }

    if (EPI <= 1) {
#pragma unroll
        for (int mt = 0; mt < 4; ++mt)
#pragma unroll
        for (int hf = 0; hf < 2; ++hf) {
            const int r = m0 + wm + mt * 16 + hf * 8 + g;
            if (r < M) {
                float* orow = out + (long)r * ostride;
#pragma unroll
                for (int nt = 0; nt < 4; ++nt) {
                    const int col = wn + nt * 8 + t4 * 2;
                    float c0 = acc[mt][nt][hf * 2 + 0] + b2[nt][0];
                    float c1 = acc[mt][nt][hf * 2 + 1] + b2[nt][1];
                    if (EPI == 1) {
                        c0 = c0 * 0.5f * (1.0f + erff(c0 * 0.70710678118654752f));
                        c1 = c1 * 0.5f * (1.0f + erff(c1 * 0.70710678118654752f));
                    }
                    if (RND) { c0 = tfr(c0); c1 = tfr(c1); }
                    *(float2*)(orow + col) = make_float2(c0, c1);
                }
            }
        }
        return;
    }

    // LN path
#pragma unroll
    for (int mt = 0; mt < 4; ++mt)
#pragma unroll
    for (int hf = 0; hf < 2; ++hf) {
        const int lr = wm + mt * 16 + hf * 8 + g;
        const int r  = m0 + lr;
        float s = 0.f, s2 = 0.f;
        const float* rrow = (EPI == 3) ? resid + (long)min(r, M - 1) * rstride : (const float*)0;
#pragma unroll
        for (int nt = 0; nt < 4; ++nt) {
            const int col = wn + nt * 8 + t4 * 2;
            float c0 = acc[mt][nt][hf * 2 + 0] + b2[nt][0];
            float c1 = acc[mt][nt][hf * 2 + 1] + b2[nt][1];
            if (EPI == 3) {
                const float2 rv = *(const float2*)(rrow + col);
                c0 += rv.x; c1 += rv.y;
            }
            acc[mt][nt][hf * 2 + 0] = c0; acc[mt][nt][hf * 2 + 1] = c1;
            s += c0 + c1; s2 += c0 * c0 + c1 * c1;
        }
        s  += __shfl_xor_sync(0xffffffffu, s, 1);
        s  += __shfl_xor_sync(0xffffffffu, s, 2);
        s2 += __shfl_xor_sync(0xffffffffu, s2, 1);
        s2 += __shfl_xor_sync(0xffffffffu, s2, 2);
        if (t4 == 0) pbuf[lr][wq] = make_float2(s, s2);
    }
    __syncthreads();
#pragma unroll
    for (int mt = 0; mt < 4; ++mt)
#pragma unroll
    for (int hf = 0; hf < 2; ++hf) {
        const int lr = wm + mt * 16 + hf * 8 + g;
        const int r  = m0 + lr;
        const float2 p0 = pbuf[lr][0], p1 = pbuf[lr][1], p2 = pbuf[lr][2], p3 = pbuf[lr][3];
        const float s    = p0.x + p1.x + p2.x + p3.x;
        const float s2   = p0.y + p1.y + p2.y + p3.y;
        const float mean = s * 0.0078125f;
        const float var  = s2 * 0.0078125f - mean * mean;
        const float rs   = rsqrtf(var + 1e-5f);
        if (r < M) {
            float* orow = out + (long)r * ostride;
#pragma unroll
            for (int nt = 0; nt < 4; ++nt) {
                const int col = wn + nt * 8 + t4 * 2;
                float o0 = (acc[mt][nt][hf * 2 + 0] - mean) * rs * lng[col]     + lnb[col];
                float o1 = (acc[mt][nt][hf * 2 + 1] - mean) * rs * lng[col + 1] + lnb[col + 1];
                if (EPI == 2) { o0 += addv[col]; o1 += addv[col + 1]; }
                if (RND) { o0 = tfr(o0); o1 = tfr(o1); }
                *(float2*)(orow + col) = make_float2(o0, o1);
            }
        }
    }
}

// ---------------------------------------------------------------------------
// GEMM core: 256 thr / 8 warps, warp tile 64x32, 3-stage BK=16 cp.async.
// k-slot permutation: fragment k slots {2*t4, 2*t4+1} on BOTH operands
// -> LDS.64 everywhere, bit-identical contraction.
// CVTA: convert A fragments (external fp32 input). B always pre-converted.
// ---------------------------------------------------------------------------
template <int EPI, int RND, int CVTA>
__device__ __forceinline__ void mma_gemm(
    const float* __restrict__ A, int lda,
    const float* __restrict__ W, int K,
    const float* __restrict__ bias,
    const float* __restrict__ lng, const float* __restrict__ lnb,
    const float* __restrict__ addv,
    const float* __restrict__ resid, int rstride,
    float* __restrict__ out, int ostride,
    int m0, int M)
{
    extern __shared__ float smem[];

    __syncthreads();   // guard smem reuse across consecutive calls

    const int tid   = threadIdx.x;
    const int ldRow = tid >> 1;
    const int ldCol = (tid & 1) * 8;

    const float* Aptr = A + (long)min(m0 + ldRow, M - 1) * lda + ldCol;
    const float* Wptr = W + (long)ldRow * K + ldCol;

    unsigned sa[3], sw[3];
#pragma unroll
    for (int s = 0; s < 3; ++s) {
        sa[s] = (unsigned)__cvta_generic_to_shared(&smem[AS_IDX(s, ldRow, ldCol)]);
        sw[s] = (unsigned)__cvta_generic_to_shared(&smem[WS_IDX(s, ldRow, ldCol)]);
    }

    const int wid = tid >> 5, lane = tid & 31;
    const int wm = (wid & 1) * 64;
    const int wn = (wid >> 1) * 32;
    const int g  = lane >> 2, t4 = lane & 3;
    const int kp = 2 * t4;               // permuted k-slot base

    float acc[4][4][4] = {};
    const int ntiles = K >> 4;

#pragma unroll
    for (int p = 0; p < 2; ++p) {
        const int k0 = p << 4;
        cp16(sa[p],      Aptr + k0);
        cp16(sa[p] + 16, Aptr + k0 + 4);
        cp16(sw[p],      Wptr + k0);
        cp16(sw[p] + 16, Wptr + k0 + 4);
        cp_commit();
    }

    int cur = 0;
    for (int t = 0; t < ntiles; ++t) {
        if (t + 2 < ntiles) cp_wait<1>(); else cp_wait<0>();
        __syncthreads();

        if (t + 2 < ntiles) {
            const int buf = (cur + 2 >= 3) ? cur - 1 : cur + 2;
            const int k0 = (t + 2) << 4;
            cp16(sa[buf],      Aptr + k0);
            cp16(sa[buf] + 16, Aptr + k0 + 4);
            cp16(sw[buf],      Wptr + k0);
            cp16(sw[buf] + 16, Wptr + k0 + 4);
            cp_commit();
        }

#pragma unroll
        for (int ks = 0; ks < 16; ks += 8) {
            unsigned af[4][4];
#pragma unroll
            for (int mt = 0; mt < 4; ++mt) {
                const int r = wm + mt * 16 + g;
                const float2 a01 = *(const float2*)&smem[AS_IDX(cur, r,     ks + kp)];
                const float2 a23 = *(const float2*)&smem[AS_IDX(cur, r + 8, ks + kp)];
                if (CVTA) {
                    af[mt][0] = f2tf(a01.x); af[mt][2] = f2tf(a01.y);
                    af[mt][1] = f2tf(a23.x); af[mt][3] = f2tf(a23.y);
                } else {
                    af[mt][0] = __float_as_uint(a01.x); af[mt][2] = __float_as_uint(a01.y);
                    af[mt][1] = __float_as_uint(a23.x); af[mt][3] = __float_as_uint(a23.y);
                }
            }
            unsigned bf[4][2];
#pragma unroll
            for (int nt = 0; nt < 4; ++nt) {
                const int n = wn + nt * 8 + g;
                const float2 b01 = *(const float2*)&smem[WS_IDX(cur, n, ks + kp)];
                bf[nt][0] = __float_as_uint(b01.x);
                bf[nt][1] = __float_as_uint(b01.y);
            }
#pragma unroll
            for (int mt = 0; mt < 4; ++mt)
#pragma unroll
                for (int nt = 0; nt < 4; ++nt)
                    mma8(acc[mt][nt], af[mt], bf[nt]);
        }
        cur = (cur + 1 >= 3) ? 0 : cur + 1;
    }

    epi_store<EPI, RND>(acc, bias, lng, lnb, addv, resid, rstride, out, ostride, m0, M);
}

// ---------------- GEMM wrappers ----------------

__global__ __launch_bounds__(256, 2) void k_g_spatial(
    const float* __restrict__ X,
    const float* __restrict__ pb, const float* __restrict__ lng,
    const float* __restrict__ lnb, const float* __restrict__ mod, int M)
{
    mma_gemm<2, 1, 1>(X, 1280, g_wtf + WOFF_SPATIAL, 1280, pb, lng, lnb, mod,
                      nullptr, 0, g_P, 384, blockIdx.x * 128, M);
}

__global__ __launch_bounds__(256, 2) void k_g_gf(
    const float* __restrict__ Xg, const float* __restrict__ Xf,
    const float* __restrict__ pb,
    const float* __restrict__ lng, const float* __restrict__ lnb,
    const float* __restrict__ mod, int M)
{
    const int s = blockIdx.y;     // 0->grad(n=1), 1->freq(n=2)
    const int n = s + 1;
    mma_gemm<2, 1, 1>(s ? Xf : Xg, 128, g_wtf + WOFF_GF + s * 128 * 128, 128,
                      pb + n * 128, lng + n * 128, lnb + n * 128, mod + n * 128,
                      nullptr, 0, g_P + n * 128, 384, blockIdx.x * 128, M);
}

__global__ __launch_bounds__(256, 2) void k_g_qkv(
    const float* __restrict__ Bi, int M)
{
    const int s  = blockIdx.y;
    const int m0 = blockIdx.x * 128;
    const float* A = g_P + s * 128;
    float* bufs[3] = {g_q, g_k, g_v};
#pragma unroll 1
    for (int j = 0; j < 5; ++j) {
        const int woff = qkv_jobs[s][j][0];
        const int boff = qkv_jobs[s][j][1];
        const int bid  = qkv_jobs[s][j][2];
        const int ooff = qkv_jobs[s][j][3];
        mma_gemm<0, 0, 0>(A, 384, g_wtf + WOFF_INW + woff, 128, Bi + boff,
                          nullptr, nullptr, nullptr, nullptr, 0,
                          bufs[bid] + ooff, bid == 0 ? 384 : 768, m0, M);
    }
}

__global__ __launch_bounds__(256, 2) void k_g_outproj(
    const float* __restrict__ bo,
    const float* __restrict__ ag, const float* __restrict__ ab, int M)
{
    const int n = blockIdx.y;
    mma_gemm<3, 1, 0>(g_o + n * 128, 384, g_wtf + WOFF_OUTW + n * 128 * 128, 128,
                      bo + n * 128, ag + n * 128, ab + n * 128, nullptr,
                      g_P + n * 128, 384, g_x1 + n * 128, 384, blockIdx.x * 128, M);
}

__global__ __launch_bounds__(256, 2) void k_g_ffn1(
    const float* __restrict__ B1, int M)
{
    const int n  = blockIdx.y;
    const int m0 = blockIdx.x * 128;
#pragma unroll 1
    for (int tl = 0; tl < 2; ++tl)
        mma_gemm<1, 1, 0>(g_x1 + n * 128, 384,
                          g_wtf + WOFF_FFN1 + n * 256 * 128 + tl * 128 * 128, 128,
                          B1 + n * 256 + tl * 128,
                          nullptr, nullptr, nullptr, nullptr, 0,
                          g_h + n * 256 + tl * 128, 768, m0, M);
}

__global__ __launch_bounds__(256, 2) void k_g_ffn2(
    const float* __restrict__ B2,
    const float* __restrict__ fg, const float* __restrict__ fb, int M)
{
    const int n = blockIdx.y;
    mma_gemm<3, 0, 0>(g_h + n * 256, 768, g_wtf + WOFF_FFN2 + n * 128 * 256, 256,
                      B2 + n * 128, fg + n * 128, fb + n * 128, nullptr,
                      g_x1 + n * 128, 384, g_x2 + n * 128, 384, blockIdx.x * 128, M);
}

// ---------------- weight tf32 pre-convert ----------------
__global__ __launch_bounds__(256) void k_cvt(
    const float* __restrict__ src, float* __restrict__ dst, int n4)
{
    const int i = blockIdx.x * 256 + threadIdx.x;
    if (i < n4) {
        const float4 v = *(const float4*)(src + 4 * i);
        float4 o;
        o.x = tfr(v.x); o.y = tfr(v.y); o.z = tfr(v.z); o.w = tfr(v.w);
        *(float4*)(dst + 4 * i) = o;
    }
}

// ---------------- Attention + gate ----------------

__global__ __launch_bounds__(256) void k_attn(int M)
{
    const int rid = blockIdx.x * 8 + (threadIdx.x >> 5);
    if (rid >= M * 3) return;
    const int lane = threadIdx.x & 31;
    const int d4 = lane * 4;
    const long qb = (long)rid * 128;
    const long kb = (long)rid * 256;

    const float4 q4  = *(const float4*)(g_q + qb + d4);
    const float4 k04 = *(const float4*)(g_k + kb + d4);
    const float4 k14 = *(const float4*)(g_k + kb + 128 + d4);
    const float4 v04 = *(const float4*)(g_v + kb + d4);
    const float4 v14 = *(const float4*)(g_v + kb + 128 + d4);

    float s0 = q4.x * k04.x + q4.y * k04.y + q4.z * k04.z + q4.w * k04.w;
    float s1 = q4.x * k14.x + q4.y * k14.y + q4.z * k14.z + q4.w * k14.w;
#pragma unroll
    for (int o = 4; o; o >>= 1) {
        s0 += __shfl_xor_sync(0xffffffffu, s0, o);
        s1 += __shfl_xor_sync(0xffffffffu, s1, o);
    }
    const float scale = 0.17677669529663687f;
    s0 *= scale; s1 *= scale;
    const float mx = fmaxf(s0, s1);
    const float e0 = expf(s0 - mx), e1 = expf(s1 - mx);
    const float inv = 1.0f / (e0 + e1);
    const float w0 = e0 * inv, w1 = e1 * inv;

    float4 o4;   // tf32-rounded: feeds outproj GEMM as A
    o4.x = tfr(w0 * v04.x + w1 * v14.x);
    o4.y = tfr(w0 * v04.y + w1 * v14.y);
    o4.z = tfr(w0 * v04.z + w1 * v14.z);
    o4.w = tfr(w0 * v04.w + w1 * v14.w);
    *(float4*)(g_o + qb + d4) = o4;
}

__global__ __launch_bounds__(256) void k_gate(
    const float* __restrict__ gw, const float* __restrict__ gb,
    float* __restrict__ out, int M)
{
    const int b = blockIdx.x * 8 + (threadIdx.x >> 5);
    if (b >= M) return;
    const int lane = threadIdx.x & 31;
    const float* xr = g_x2 + (long)b * 384;
    float l0 = 0.f, l1 = 0.f, l2 = 0.f;
#pragma unroll
    for (int j = 0; j < 12; ++j) {
        const int idx = lane + 32 * j;
        const float x = xr[idx];
        l0 += x * gw[idx];
        l1 += x * gw[384 + idx];
        l2 += x * gw[768 + idx];
    }
#pragma unroll
    for (int o = 16; o; o >>= 1) {
        l0 += __shfl_xor_sync(0xffffffffu, l0, o);
        l1 += __shfl_xor_sync(0xffffffffu, l1, o);
        l2 += __shfl_xor_sync(0xffffffffu, l2, o);
    }
    l0 += gb[0]; l1 += gb[1]; l2 += gb[2];
    const float mx = fmaxf(l0, fmaxf(l1, l2));
    const float e0 = expf(l0 - mx), e1 = expf(l1 - mx), e2 = expf(l2 - mx);
    const float inv = 1.0f / (e0 + e1 + e2);
    const float w0 = e0 * inv, w1 = e1 * inv, w2 = e2 * inv;
#pragma unroll
    for (int j = 0; j < 4; ++j) {
        const int d = lane + 32 * j;
        out[(long)b * 128 + d] = w0 * xr[d] + w1 * xr[128 + d] + w2 * xr[256 + d];
    }
}

// ---------------------------------------------------------------------------

extern "C" void kernel_launch(void* const* d_in, const int* in_sizes, int n_in,
                              void* d_out, int out_size)
{
    const float* x_spatial   = (const float*)d_in[0];
    const float* x_gradient  = (const float*)d_in[1];
    const float* x_frequency = (const float*)d_in[2];
    const float* w_spatial   = (const float*)d_in[3];
    const float* w_gf        = (const float*)d_in[4];
    const float* proj_b      = (const float*)d_in[5];
    const float* proj_ln_g   = (const float*)d_in[6];
    const float* proj_ln_b   = (const float*)d_in[7];
    const float* mod_emb     = (const float*)d_in[8];
    const float* in_w        = (const float*)d_in[9];
    const float* in_b        = (const float*)d_in[10];
    const float* out_w       = (const float*)d_in[11];
    const float* out_b       = (const float*)d_in[12];
    const float* attn_g      = (const float*)d_in[13];
    const float* attn_b      = (const float*)d_in[14];
    const float* w1          = (const float*)d_in[15];
    const float* b1          = (const float*)d_in[16];
    const float* w2          = (const float*)d_in[17];
    const float* b2          = (const float*)d_in[18];
    const float* ffn_g       = (const float*)d_in[19];
    const float* ffn_b       = (const float*)d_in[20];
    const float* gate_w      = (const float*)d_in[21];
    const float* gate_b      = (const float*)d_in[22];
    float* out = (float*)d_out;

    static int smem_set = 0;
    if (!smem_set) {
        cudaFuncSetAttribute(k_g_spatial, cudaFuncAttributeMaxDynamicSharedMemorySize, GSMEM);
        cudaFuncSetAttribute(k_g_gf,      cudaFuncAttributeMaxDynamicSharedMemorySize, GSMEM);
        cudaFuncSetAttribute(k_g_qkv,     cudaFuncAttributeMaxDynamicSharedMemorySize, GSMEM);
        cudaFuncSetAttribute(k_g_outproj, cudaFuncAttributeMaxDynamicSharedMemorySize, GSMEM);
        cudaFuncSetAttribute(k_g_ffn1,    cudaFuncAttributeMaxDynamicSharedMemorySize, GSMEM);
        cudaFuncSetAttribute(k_g_ffn2,    cudaFuncAttributeMaxDynamicSharedMemorySize, GSMEM);
        smem_set = 1;
    }

    int B = in_sizes[0] / 1280;
    if (B > MAXB) B = MAXB;
    const int gm = (B + 127) / 128;
    const int R  = B * 3;

    float* wtf;
    cudaGetSymbolAddress((void**)&wtf, g_wtf);
    k_cvt<<<(163840/4 + 255)/256, 256>>>(w_spatial, wtf + WOFF_SPATIAL, 163840/4);
    k_cvt<<<( 32768/4 + 255)/256, 256>>>(w_gf,      wtf + WOFF_GF,       32768/4);
    k_cvt<<<(147456/4 + 255)/256, 256>>>(in_w,      wtf + WOFF_INW,     147456/4);
    k_cvt<<<( 49152/4 + 255)/256, 256>>>(out_w,     wtf + WOFF_OUTW,     49152/4);
    k_cvt<<<( 98304/4 + 255)/256, 256>>>(w1,        wtf + WOFF_FFN1,     98304/4);
    k_cvt<<<( 98304/4 + 255)/256, 256>>>(w2,        wtf + WOFF_FFN2,     98304/4);

    k_g_spatial<<<gm, 256, GSMEM>>>(x_spatial, proj_b, proj_ln_g, proj_ln_b, mod_emb, B);
    k_g_gf<<<dim3(gm, 2), 256, GSMEM>>>(x_gradient, x_frequency, proj_b,
                                        proj_ln_g, proj_ln_b, mod_emb, B);
    k_g_qkv<<<dim3(gm, 3), 256, GSMEM>>>(in_b, B);
    k_attn<<<(R + 7) / 8, 256>>>(B);
    k_g_outproj<<<dim3(gm, 3), 256, GSMEM>>>(out_b, attn_g, attn_b, B);
    k_g_ffn1<<<dim3(gm, 3), 256, GSMEM>>>(b1, B);
    k_g_ffn2<<<dim3(gm, 3), 256, GSMEM>>>(b2, ffn_g, ffn_b, B);
    k_gate<<<(B + 7) / 8, 256>>>(gate_w, gate_b, out, B);
}